// round 15
// baseline (speedup 1.0000x reference)
#include <cuda_runtime.h>
#include <cuda_bf16.h>
#include <cstdint>

// Shapes
#define VSZ   32000
#define ESZ   512
#define HSZ   512
#define BSZ   64
#define TSZ   65          // sequence steps
#define G3    1536        // 3*H
#define MROWS (BSZ*TSZ)   // 4160 output rows
#define BH    (BSZ*HSZ)

#define NC    64          // scan CTAs (first 64 of the fused grid)
#define NCTA  148         // fused grid (1 CTA/SM, all co-resident)
#define JC    8           // j-columns per scan CTA
#define WB    520         // bf16 row stride (512+8)
#define NT    384         // threads (12 warps)

#define LG_STRIDE 72
#define AS_BUF    (192 * LG_STRIDE)   // one A stage (192 rows)
#define BS_BUF    (128 * LG_STRIDE)   // one B stage (128 rows)
#define NMU       22                  // ceil(4160 / 192)
#define NITEM     (NMU * 250)
#define NGI       (33 * 12)           // GI0 tiles: 33 m-tiles x 12 n-tiles

// ---------------- device scratch (static allocations only) ----------------
__device__ float          g_HA[2 * BH];
__device__ float          g_HB[2 * BH];
__device__ __nv_bfloat16  g_HAb[2 * BH];
__device__ __nv_bfloat16  g_HBb[2 * BH];
__device__ float          g_GI0[TSZ * BSZ * G3];        // [t][b][G3], 25.6 MB
__device__ __nv_bfloat16  g_WFCb[(size_t)VSZ * HSZ];    // 32.8 MB
__device__ __nv_bfloat16  g_YSb[(size_t)MROWS * HSZ];   // [t*64+b] layout
__device__ float          g_SUMEXP[MROWS];              // indexed by orow=b*65+t
__device__ unsigned       g_cnt;
__device__ unsigned       g_tick;
__device__ unsigned       g_gtick;
__device__ unsigned       g_gidone;
__device__ unsigned       g_ldone;

__device__ __forceinline__ float sigf(float x) { return 1.f / (1.f + __expf(-x)); }

__device__ __forceinline__ void mma16816(float* c, const uint32_t* a, uint32_t b0, uint32_t b1)
{
    asm volatile(
        "mma.sync.aligned.m16n8k16.row.col.f32.bf16.bf16.f32 "
        "{%0,%1,%2,%3}, {%4,%5,%6,%7}, {%8,%9}, {%0,%1,%2,%3};\n"
        : "+f"(c[0]), "+f"(c[1]), "+f"(c[2]), "+f"(c[3])
        : "r"(a[0]), "r"(a[1]), "r"(a[2]), "r"(a[3]), "r"(b0), "r"(b1));
}

// scan grid barrier: RED arrive + LOAD-based polling (R8 proven)
__device__ __forceinline__ void gbar(unsigned target) {
    __syncthreads();
    if (threadIdx.x == 0) {
        unsigned* p = &g_cnt;
        asm volatile("red.release.gpu.global.add.u32 [%0], 1;" :: "l"(p) : "memory");
        unsigned v;
        do {
            asm volatile("ld.acquire.gpu.global.u32 %0, [%1];" : "=r"(v) : "l"(p) : "memory");
        } while (v < target);
    }
    __syncthreads();
}

__device__ __forceinline__ void poll_ge(unsigned* p, unsigned target, int ns) {
    unsigned v;
    for (;;) {
        asm volatile("ld.acquire.gpu.global.u32 %0, [%1];" : "=r"(v) : "l"(p) : "memory");
        if (v >= target) break;
        __nanosleep(ns);
    }
}

__device__ __forceinline__ void rel_inc(unsigned* p) {
    asm volatile("red.release.gpu.global.add.u32 [%0], 1;" :: "l"(p) : "memory");
}

#define CPA16(d, s) asm volatile("cp.async.cg.shared.global [%0], [%1], 16;" :: "r"(d), "l"(s) : "memory")
#define CPC()       asm volatile("cp.async.commit_group;" ::: "memory")
#define CPW(n)      asm volatile("cp.async.wait_group %0;" :: "n"(n) : "memory")

// ---------------- h0 + zero counters --------------------------------------
__global__ void k_h0(const float* __restrict__ ctx,
                     const float* __restrict__ W_init,
                     const float* __restrict__ b_init)
{
    const int lb = blockIdx.x;
    const int l = lb >> 6, b = lb & 63;
    const int tid = threadIdx.x;
    __shared__ float cs[HSZ];
    ((float4*)cs)[tid] = ((const float4*)(ctx + (size_t)lb * HSZ))[tid];

    const int gid = blockIdx.x * 128 + tid;
    if (gid < MROWS) g_SUMEXP[gid] = 0.f;
    if (gid == 0) { g_cnt = 0; g_tick = 0; g_gtick = 0; g_gidone = 0; g_ldone = 0; }
    __syncthreads();

    float*         hout  = (l == 0) ? g_HA  : g_HB;
    __nv_bfloat16* houtb = (l == 0) ? g_HAb : g_HBb;
#pragma unroll
    for (int jj = 0; jj < 4; jj++) {
        const int j = tid * 4 + jj;
        const float* wr = W_init + (size_t)j * HSZ;
        float acc = 0.f;
        for (int k = 0; k < HSZ; k += 4) {
            float4 w = *(const float4*)(wr + k);
            acc += w.x * cs[k] + w.y * cs[k+1] + w.z * cs[k+2] + w.w * cs[k+3];
        }
        float v = tanhf(acc + b_init[j]);
        hout[b * HSZ + j]  = v;
        houtb[b * HSZ + j] = __float2bfloat16(v);
    }
}

// ---------------- W_fc fp32 -> bf16 ---------------------------------------
__global__ void k_cvt_wfc(const float* __restrict__ wfc)
{
    const size_t i = (size_t)blockIdx.x * 256 + threadIdx.x;
    float4 v = ((const float4*)wfc)[i];
    __nv_bfloat162 lo = __floats2bfloat162_rn(v.x, v.y);
    __nv_bfloat162 hi = __floats2bfloat162_rn(v.z, v.w);
    uint2 o; o.x = *(uint32_t*)&lo; o.y = *(uint32_t*)&hi;
    ((uint2*)g_WFCb)[i] = o;
}

// ---------------- FUSED: scan + GI0 producers + logits consumers + fix ----
__global__ void __launch_bounds__(NT, 1) k_fused(
    const float* __restrict__ Wh0, const float* __restrict__ bh0,
    const float* __restrict__ Wi1, const float* __restrict__ Wh1,
    const float* __restrict__ bi1, const float* __restrict__ bh1,
    const float* __restrict__ b_fc, float* __restrict__ out,
    const float* __restrict__ emb, const int* __restrict__ targets,
    const float* __restrict__ Wi0, const float* __restrict__ bi0)
{
    extern __shared__ __nv_bfloat16 smb[];
    __shared__ int s_w;

    const int tid  = threadIdx.x;
    const int wid  = tid >> 5, lane = tid & 31;
    const int g    = lane >> 2, tg = lane & 3;

    // =================== SCAN ROLE (CTAs 0..63) ===================
    if (blockIdx.x < NC) {
        __nv_bfloat16* Wh0s = smb;
        __nv_bfloat16* Wi1s = smb + 24 * WB;
        __nv_bfloat16* Wh1s = smb + 48 * WB;
        __nv_bfloat16* Ax   = smb + 72 * WB;
        __nv_bfloat16* Ah   = Ax  + 64 * WB;
        float4* accS = (float4*)(smb + 200 * WB);

        const int mt   = wid & 3;
        const int mat  = wid >> 2;
        const int m0   = mt * 16;
        const int jb   = blockIdx.x * JC;

        for (int idx = tid; idx < 24 * 128; idx += NT) {
            const int row = idx >> 7, q = idx & 127;
            const int gate = row >> 3, jj = row & 7;
            const size_t grow = (size_t)(gate * HSZ + jb + jj) * HSZ + q * 4;
            const int o = row * WB + q * 4;
            float4 v0 = *(const float4*)(Wh0 + grow);
            float4 v1 = *(const float4*)(Wi1 + grow);
            float4 v2 = *(const float4*)(Wh1 + grow);
            __nv_bfloat162 p0, p1; uint2 u;
            p0 = __floats2bfloat162_rn(v0.x, v0.y); p1 = __floats2bfloat162_rn(v0.z, v0.w);
            u.x = *(uint32_t*)&p0; u.y = *(uint32_t*)&p1; *(uint2*)(Wh0s + o) = u;
            p0 = __floats2bfloat162_rn(v1.x, v1.y); p1 = __floats2bfloat162_rn(v1.z, v1.w);
            u.x = *(uint32_t*)&p0; u.y = *(uint32_t*)&p1; *(uint2*)(Wi1s + o) = u;
            p0 = __floats2bfloat162_rn(v2.x, v2.y); p1 = __floats2bfloat162_rn(v2.z, v2.w);
            u.x = *(uint32_t*)&p0; u.y = *(uint32_t*)&p1; *(uint2*)(Wh1s + o) = u;
        }
        __syncthreads();

        float bg0[3][2], bgi1[3][2], bgh1[3][2];
#pragma unroll
        for (int gi = 0; gi < 3; gi++)
#pragma unroll
            for (int cc = 0; cc < 2; cc++) {
                const int j = gi * HSZ + jb + 2 * tg + cc;
                bg0[gi][cc]  = bh0[j];
                bgi1[gi][cc] = bi1[j];
                bgh1[gi][cc] = bh1[j];
            }

        auto mma3 = [&](const __nv_bfloat16* A, const __nv_bfloat16* W, float acc[3][4]) {
            const __nv_bfloat16* Ar0 = A + (m0 + g) * WB;
            const __nv_bfloat16* Ar1 = Ar0 + 8 * WB;
#pragma unroll
            for (int gi = 0; gi < 3; gi++)
#pragma unroll
                for (int r = 0; r < 4; r++) acc[gi][r] = 0.f;
#pragma unroll
            for (int ks = 0; ks < 32; ks++) {
                const int k = ks * 16;
                uint32_t a[4];
                a[0] = *(const uint32_t*)(Ar0 + k + tg * 2);
                a[1] = *(const uint32_t*)(Ar1 + k + tg * 2);
                a[2] = *(const uint32_t*)(Ar0 + k + 8 + tg * 2);
                a[3] = *(const uint32_t*)(Ar1 + k + 8 + tg * 2);
#pragma unroll
                for (int gi = 0; gi < 3; gi++) {
                    const __nv_bfloat16* br = W + (gi * 8 + g) * WB + k + tg * 2;
                    mma16816(acc[gi], a, *(const uint32_t*)br, *(const uint32_t*)(br + 8));
                }
            }
        };

        auto epi0 = [&](int tt, const float acc0[3][4]) {
            const float* hAin = g_HA + (tt & 1) * BH;
            float* hAout = g_HA + ((tt & 1) ^ 1) * BH;
            __nv_bfloat16* hAbout = g_HAb + ((tt & 1) ^ 1) * BH;
#pragma unroll
            for (int hf = 0; hf < 2; hf++) {
                const int b = m0 + g + 8 * hf;
                const float* gi0p = g_GI0 + ((size_t)tt * BSZ + b) * G3;
#pragma unroll
                for (int cc = 0; cc < 2; cc++) {
                    const int j = jb + 2 * tg + cc;
                    const float r = sigf(__ldcg(gi0p + j)          + acc0[0][hf*2+cc] + bg0[0][cc]);
                    const float z = sigf(__ldcg(gi0p + HSZ + j)    + acc0[1][hf*2+cc] + bg0[1][cc]);
                    const float n = tanhf(__ldcg(gi0p + 2*HSZ + j) + r * (acc0[2][hf*2+cc] + bg0[2][cc]));
                    const float hprev = __ldcg(hAin + (size_t)b * HSZ + j);
                    const float v = (1.f - z) * n + z * hprev;
                    hAout[(size_t)b * HSZ + j]  = v;
                    hAbout[(size_t)b * HSZ + j] = __float2bfloat16(v);
                }
            }
        };

        // prologue: cell0(t=0) — wait for GI0 m-tile 0 (12 n-tiles)
        {
            for (int idx = tid; idx < 64 * 64; idx += NT) {
                const int r = idx >> 6, q = idx & 63;
                *(uint4*)(Ax + r * WB + q * 8) =
                    __ldcg((const uint4*)(g_HAb + (size_t)r * HSZ + q * 8));
            }
            if (tid == 0) poll_ge(&g_gidone, 12u, 128);
            __syncthreads();
            if (mat == 1) {
                float acc0[3][4];
                mma3(Ax, Wh0s, acc0);
                epi0(0, acc0);
            }
        }
        gbar(NC);

        for (int t = 0; t < TSZ; t++) {
            const int cur = t & 1, nxt = cur ^ 1;

            {
                const __nv_bfloat16* srcA = g_HAb + (size_t)nxt * BH;
                const __nv_bfloat16* srcB = g_HBb + (size_t)cur * BH;
                for (int idx = tid; idx < 128 * 64; idx += NT) {
                    const int r = idx >> 6, q = idx & 63;
                    if (r < 64)
                        *(uint4*)(Ax + r * WB + q * 8) =
                            __ldcg((const uint4*)(srcA + (size_t)r * HSZ + q * 8));
                    else
                        *(uint4*)(Ah + (r - 64) * WB + q * 8) =
                            __ldcg((const uint4*)(srcB + (size_t)(r - 64) * HSZ + q * 8));
                }
            }
            __syncthreads();

            float acc[3][4];
            if (mat == 0)      mma3(Ax, Wi1s, acc);
            else if (mat == 1) mma3(Ax, Wh0s, acc);
            else               mma3(Ah, Wh1s, acc);

            if (mat == 0) {
#pragma unroll
                for (int gi = 0; gi < 3; gi++) {
                    float4 v; v.x = acc[gi][0]; v.y = acc[gi][1]; v.z = acc[gi][2]; v.w = acc[gi][3];
                    accS[((wid & 3) * 3 + gi) * 32 + lane] = v;
                }
            }
            // GI0 availability for epi0(t+1): m-tile (t+1)/2 complete
            if (tid == 0 && t < TSZ - 1)
                poll_ge(&g_gidone, (unsigned)(((t + 1) >> 1) + 1) * 12u, 128);
            __syncthreads();

            if (mat == 2) {
                const float* hBin = g_HB + (size_t)cur * BH;
                float* hBout = g_HB + (size_t)nxt * BH;
                __nv_bfloat16* hBbout = g_HBb + (size_t)nxt * BH;
                float accx[3][4];
#pragma unroll
                for (int gi = 0; gi < 3; gi++) {
                    float4 v = accS[((wid & 3) * 3 + gi) * 32 + lane];
                    accx[gi][0] = v.x; accx[gi][1] = v.y; accx[gi][2] = v.z; accx[gi][3] = v.w;
                }
#pragma unroll
                for (int hf = 0; hf < 2; hf++) {
                    const int b = m0 + g + 8 * hf;
#pragma unroll
                    for (int cc = 0; cc < 2; cc++) {
                        const int j = jb + 2 * tg + cc;
                        const float r = sigf(accx[0][hf*2+cc] + bgi1[0][cc] + acc[0][hf*2+cc] + bgh1[0][cc]);
                        const float z = sigf(accx[1][hf*2+cc] + bgi1[1][cc] + acc[1][hf*2+cc] + bgh1[1][cc]);
                        const float n = tanhf(accx[2][hf*2+cc] + bgi1[2][cc]
                                              + r * (acc[2][hf*2+cc] + bgh1[2][cc]));
                        const float hprev = __ldcg(hBin + (size_t)b * HSZ + j);
                        const float v = (1.f - z) * n + z * hprev;
                        hBout[(size_t)b * HSZ + j]  = v;
                        hBbout[(size_t)b * HSZ + j] = __float2bfloat16(v);
                        g_YSb[((size_t)t * BSZ + b) * HSZ + j] = __float2bfloat16(v);  // [t*64+b]
                    }
                }
            } else if (mat == 1 && t < TSZ - 1) {
                epi0(t + 1, acc);
            }

            if (t < TSZ - 1) gbar((unsigned)(t + 2) * NC);
        }

        // publish final step (t=64) writes
        __syncthreads();
        if (tid == 0) rel_inc(&g_cnt);
    }

    // =================== GI0 PRODUCER ROLE (consumers; empty for scan CTAs)
    {
        __nv_bfloat16* Ag = smb;                       // [128][72]
        __nv_bfloat16* Bg = smb + 128 * LG_STRIDE;     // [128][72]
        float* bsg = (float*)(Bg + 128 * LG_STRIDE);   // 128 floats
        int*   tkg = (int*)(bsg + 128);                // 128 ints
        const int warp_m = wid >> 2, warp_n = wid & 3; // 2x4 (wid<8 compute)

        for (;;) {
            if (tid == 0) s_w = (int)atomicAdd(&g_gtick, 1u);
            __syncthreads();
            const int w = s_w;
            if (w >= NGI) break;
            const int mu = w / 12, nbk = w % 12;
            const int bm = mu * 128, bn = nbk * 128;

            if (tid < 128) {
                bsg[tid] = bi0[bn + tid];
                int row = bm + tid; if (row >= MROWS) row = MROWS - 1;
                const int t = row >> 6, b = row & 63;
                tkg[tid] = (t == 0) ? 1 : targets[b * TSZ + t - 1];
            }
            __syncthreads();

            float acc[4][4][4];
#pragma unroll
            for (int i = 0; i < 4; i++)
#pragma unroll
                for (int j = 0; j < 4; j++)
#pragma unroll
                    for (int r = 0; r < 4; r++) acc[i][j][r] = 0.f;

            for (int k0 = 0; k0 < ESZ; k0 += 64) {
                for (int i = tid; i < 2048; i += NT) {
                    const int r = i >> 4, q = i & 15;
                    float4 v = *(const float4*)(emb + (size_t)tkg[r] * ESZ + k0 + q * 4);
                    __nv_bfloat162 p0 = __floats2bfloat162_rn(v.x, v.y);
                    __nv_bfloat162 p1 = __floats2bfloat162_rn(v.z, v.w);
                    uint2 u; u.x = *(uint32_t*)&p0; u.y = *(uint32_t*)&p1;
                    *(uint2*)(Ag + r * LG_STRIDE + q * 4) = u;
                }
                for (int i = tid; i < 2048; i += NT) {
                    const int r = i >> 4, q = i & 15;
                    float4 v = *(const float4*)(Wi0 + (size_t)(bn + r) * ESZ + k0 + q * 4);
                    __nv_bfloat162 p0 = __floats2bfloat162_rn(v.x, v.y);
                    __nv_bfloat162 p1 = __floats2bfloat162_rn(v.z, v.w);
                    uint2 u; u.x = *(uint32_t*)&p0; u.y = *(uint32_t*)&p1;
                    *(uint2*)(Bg + r * LG_STRIDE + q * 4) = u;
                }
                __syncthreads();
                if (wid < 8) {
#pragma unroll
                    for (int kk = 0; kk < 64; kk += 16) {
                        uint32_t af[4][4], bfr[4][2];
#pragma unroll
                        for (int im = 0; im < 4; im++) {
                            int r0 = warp_m * 64 + im * 16;
                            af[im][0] = *(const uint32_t*)(Ag + (r0 + g    ) * LG_STRIDE + kk + tg*2    );
                            af[im][1] = *(const uint32_t*)(Ag + (r0 + g + 8) * LG_STRIDE + kk + tg*2    );
                            af[im][2] = *(const uint32_t*)(Ag + (r0 + g    ) * LG_STRIDE + kk + tg*2 + 8);
                            af[im][3] = *(const uint32_t*)(Ag + (r0 + g + 8) * LG_STRIDE + kk + tg*2 + 8);
                        }
#pragma unroll
                        for (int in_ = 0; in_ < 4; in_++) {
                            int c0 = warp_n * 32 + in_ * 8;
                            bfr[in_][0] = *(const uint32_t*)(Bg + (c0 + g) * LG_STRIDE + kk + tg*2    );
                            bfr[in_][1] = *(const uint32_t*)(Bg + (c0 + g) * LG_STRIDE + kk + tg*2 + 8);
                        }
#pragma unroll
                        for (int im = 0; im < 4; im++)
#pragma unroll
                            for (int in_ = 0; in_ < 4; in_++)
                                mma16816(acc[im][in_], af[im], bfr[in_][0], bfr[in_][1]);
                    }
                }
                __syncthreads();
            }

            if (wid < 8) {
#pragma unroll
                for (int im = 0; im < 4; im++) {
#pragma unroll
                    for (int half = 0; half < 2; half++) {
                        const int row = bm + warp_m * 64 + im * 16 + g + half * 8;
                        if (row >= MROWS) continue;
#pragma unroll
                        for (int in_ = 0; in_ < 4; in_++) {
                            const int col_l = warp_n * 32 + in_ * 8 + tg * 2;
                            float2 st;
                            st.x = acc[im][in_][half*2 + 0] + bsg[col_l];
                            st.y = acc[im][in_][half*2 + 1] + bsg[col_l + 1];
                            *(float2*)(g_GI0 + (size_t)row * G3 + bn + col_l) = st;
                        }
                    }
                }
            }
            __syncthreads();
            if (tid == 0) rel_inc(&g_gidone);
        }
    }

    // =================== LOGITS CONSUMER ROLE: 192m x 128n, 12 warps =======
    {
        __nv_bfloat16* As = smb;                       // [2][192][72]
        __nv_bfloat16* Bs = smb + 2 * AS_BUF;          // [2][128][72]
        float* bsm = (float*)(Bs + 2 * BS_BUF);        // 128
        float* ses = bsm + 128;                        // 192

        const int warp_m = wid >> 2, warp_n = wid & 3; // 3 x 4 warps

        for (;;) {
            if (tid == 0) s_w = (int)atomicAdd(&g_tick, 1u);
            __syncthreads();
            const int w = s_w;
            if (w >= NITEM) break;
            const int mu = w / 250, nb = w % 250;
            const int bm = mu * 192, bn = nb * 128;
            const int need_t = (3 * mu + 2 < TSZ - 1) ? (3 * mu + 2) : (TSZ - 1);
            const unsigned wait_val = (unsigned)(need_t + 2) * NC;

            if (tid == 0) poll_ge(&g_cnt, wait_val, 256);
            if (tid < 128) bsm[tid] = b_fc[bn + tid];
            if (tid < 192) ses[tid] = 0.f;
            __syncthreads();

            float acc[4][4][4];
#pragma unroll
            for (int i = 0; i < 4; i++)
#pragma unroll
                for (int j = 0; j < 4; j++)
#pragma unroll
                    for (int r = 0; r < 4; r++) acc[i][j][r] = 0.f;

            {
#pragma unroll
                for (int it = 0; it < 4; it++) {
                    const int idx = it * NT + tid;
                    const int r = idx >> 3, q = idx & 7;
                    int row = bm + r; if (row >= MROWS) row = MROWS - 1;
                    uint32_t d = (uint32_t)__cvta_generic_to_shared(As + r * LG_STRIDE + q * 8);
                    CPA16(d, g_YSb + (size_t)row * HSZ + q * 8);
                }
                for (int idx = tid; idx < 1024; idx += NT) {
                    const int r = idx >> 3, q = idx & 7;
                    uint32_t d = (uint32_t)__cvta_generic_to_shared(Bs + r * LG_STRIDE + q * 8);
                    CPA16(d, g_WFCb + (size_t)(bn + r) * HSZ + q * 8);
                }
            }
            CPC();

            for (int i = 0; i < 8; i++) {
                const int p = i & 1;
                if (i + 1 < 8) {
                    const int k0 = (i + 1) * 64, pn = p ^ 1;
#pragma unroll
                    for (int it = 0; it < 4; it++) {
                        const int idx = it * NT + tid;
                        const int r = idx >> 3, q = idx & 7;
                        int row = bm + r; if (row >= MROWS) row = MROWS - 1;
                        uint32_t d = (uint32_t)__cvta_generic_to_shared(As + pn * AS_BUF + r * LG_STRIDE + q * 8);
                        CPA16(d, g_YSb + (size_t)row * HSZ + k0 + q * 8);
                    }
                    for (int idx = tid; idx < 1024; idx += NT) {
                        const int r = idx >> 3, q = idx & 7;
                        uint32_t d = (uint32_t)__cvta_generic_to_shared(Bs + pn * BS_BUF + r * LG_STRIDE + q * 8);
                        CPA16(d, g_WFCb + (size_t)(bn + r) * HSZ + k0 + q * 8);
                    }
                    CPC(); CPW(1);
                } else CPW(0);
                __syncthreads();

                const __nv_bfloat16* Ap = As + p * AS_BUF;
                const __nv_bfloat16* Bp = Bs + p * BS_BUF;
#pragma unroll
                for (int kk = 0; kk < 64; kk += 16) {
                    uint32_t af[4][4], bfr[4][2];
#pragma unroll
                    for (int im = 0; im < 4; im++) {
                        int r0 = warp_m * 64 + im * 16;
                        af[im][0] = *(const uint32_t*)(Ap + (r0 + g    ) * LG_STRIDE + kk + tg*2    );
                        af[im][1] = *(const uint32_t*)(Ap + (r0 + g + 8) * LG_STRIDE + kk + tg*2    );
                        af[im][2] = *(const uint32_t*)(Ap + (r0 + g    ) * LG_STRIDE + kk + tg*2 + 8);
                        af[im][3] = *(const uint32_t*)(Ap + (r0 + g + 8) * LG_STRIDE + kk + tg*2 + 8);
                    }
#pragma unroll
                    for (int in_ = 0; in_ < 4; in_++) {
                        int c0 = warp_n * 32 + in_ * 8;
                        bfr[in_][0] = *(const uint32_t*)(Bp + (c0 + g) * LG_STRIDE + kk + tg*2    );
                        bfr[in_][1] = *(const uint32_t*)(Bp + (c0 + g) * LG_STRIDE + kk + tg*2 + 8);
                    }
#pragma unroll
                    for (int im = 0; im < 4; im++)
#pragma unroll
                        for (int in_ = 0; in_ < 4; in_++)
                            mma16816(acc[im][in_], af[im], bfr[in_][0], bfr[in_][1]);
                }
                __syncthreads();
            }

#pragma unroll
            for (int im = 0; im < 4; im++) {
#pragma unroll
                for (int half = 0; half < 2; half++) {
                    const int row_l = warp_m * 64 + im * 16 + g + half * 8;
                    const int r_ys = bm + row_l;
                    if (r_ys >= MROWS) continue;
                    const int orow = (r_ys & 63) * TSZ + (r_ys >> 6);
                    float s = 0.f;
#pragma unroll
                    for (int in_ = 0; in_ < 4; in_++) {
                        const int col_l = warp_n * 32 + in_ * 8 + tg * 2;
                        float v0 = acc[im][in_][half*2 + 0] + bsm[col_l];
                        float v1 = acc[im][in_][half*2 + 1] + bsm[col_l + 1];
                        float2 st; st.x = v0; st.y = v1;
                        *(float2*)(out + (size_t)orow * VSZ + bn + col_l) = st;
                        s += __expf(v0) + __expf(v1);
                    }
                    atomicAdd(&ses[row_l], s);
                }
            }
            __syncthreads();
            if (tid < 192) {
                const int r_ys = bm + tid;
                if (r_ys < MROWS) {
                    const int orow = (r_ys & 63) * TSZ + (r_ys >> 6);
                    atomicAdd(&g_SUMEXP[orow], ses[tid]);
                }
            }
            __syncthreads();
            if (tid == 0) rel_inc(&g_ldone);
        }
    }

    // =================== FIX ROLE: wait all tiles, sweep ===================
    {
        if (tid == 0) poll_ge(&g_ldone, (unsigned)NITEM, 512);
        __syncthreads();

        for (int orow = blockIdx.x; orow < MROWS; orow += NCTA) {
            const float l = __logf(__ldcg(&g_SUMEXP[orow]));
            float4* base = (float4*)(out + (size_t)orow * VSZ);
            for (int q = tid; q < VSZ / 4; q += NT) {
                float4 v = __ldcg(base + q);
                v.x -= l; v.y -= l; v.z -= l; v.w -= l;
                base[q] = v;
            }
        }
    }
}

// ---------------- launch ---------------------------------------------------
extern "C" void kernel_launch(void* const* d_in, const int* in_sizes, int n_in,
                              void* d_out, int out_size)
{
    const float* ctx     = (const float*)d_in[0];
    const int*   targets = (const int*)  d_in[1];
    const float* emb     = (const float*)d_in[2];
    const float* W_init  = (const float*)d_in[3];
    const float* b_init  = (const float*)d_in[4];
    const float* Wi0     = (const float*)d_in[5];
    const float* Wh0     = (const float*)d_in[6];
    const float* bi0     = (const float*)d_in[7];
    const float* bh0     = (const float*)d_in[8];
    const float* Wi1     = (const float*)d_in[9];
    const float* Wh1     = (const float*)d_in[10];
    const float* bi1     = (const float*)d_in[11];
    const float* bh1     = (const float*)d_in[12];
    const float* W_fc    = (const float*)d_in[13];
    const float* b_fc    = (const float*)d_in[14];
    float* out = (float*)d_out;

    static int smem_set = 0;
    const int fused_smem = 200 * WB * 2 + 4 * 3 * 32 * 16;   // 214,144 B
    if (!smem_set) {
        cudaFuncSetAttribute(k_fused, cudaFuncAttributeMaxDynamicSharedMemorySize, fused_smem);
        smem_set = 1;
    }

    k_h0<<<128, 128>>>(ctx, W_init, b_init);
    k_cvt_wfc<<<(VSZ * HSZ / 4) / 256, 256>>>(W_fc);

    k_fused<<<NCTA, NT, fused_smem>>>(Wh0, bh0, Wi1, Wh1, bi1, bh1, b_fc, out,
                                      emb, targets, Wi0, bi0);
}

// round 16
// speedup vs baseline: 1.0949x; 1.0949x over previous
#include <cuda_runtime.h>
#include <cuda_bf16.h>
#include <cstdint>

// Shapes
#define VSZ   32000
#define ESZ   512
#define HSZ   512
#define BSZ   64
#define TSZ   65          // sequence steps
#define G3    1536        // 3*H
#define MROWS (BSZ*TSZ)   // 4160 output rows
#define BH    (BSZ*HSZ)

#define NC    64          // scan CTAs (first 64 of the fused grid)
#define NCTA  148         // fused grid (1 CTA/SM, all co-resident)
#define JC    8           // j-columns per scan CTA
#define WB    520         // bf16 row stride (512+8)
#define NT    384         // threads (12 warps)

#define LG_STRIDE 72
#define AS_BUF    (192 * LG_STRIDE)   // one A stage (192 rows)
#define BS_BUF    (128 * LG_STRIDE)   // one B stage (128 rows)
#define NMU       22                  // ceil(4160 / 192)
#define NITEM     (NMU * 250)

// ---------------- device scratch (static allocations only) ----------------
__device__ float          g_HA[2 * BH];
__device__ float          g_HB[2 * BH];
__device__ __nv_bfloat16  g_HAb[2 * BH];
__device__ __nv_bfloat16  g_HBb[2 * BH];
__device__ float          g_GI0[TSZ * BSZ * G3];        // 25.6 MB
__device__ __nv_bfloat16  g_WFCb[(size_t)VSZ * HSZ];    // 32.8 MB
__device__ __nv_bfloat16  g_YSb[(size_t)MROWS * HSZ];   // [t*64+b] layout
__device__ float          g_SUMEXP[MROWS];              // indexed by orow=b*65+t
__device__ unsigned       g_cnt;
__device__ unsigned       g_tick;

__device__ __forceinline__ float sigf(float x) { return 1.f / (1.f + __expf(-x)); }

__device__ __forceinline__ void mma16816(float* c, const uint32_t* a, uint32_t b0, uint32_t b1)
{
    asm volatile(
        "mma.sync.aligned.m16n8k16.row.col.f32.bf16.bf16.f32 "
        "{%0,%1,%2,%3}, {%4,%5,%6,%7}, {%8,%9}, {%0,%1,%2,%3};\n"
        : "+f"(c[0]), "+f"(c[1]), "+f"(c[2]), "+f"(c[3])
        : "r"(a[0]), "r"(a[1]), "r"(a[2]), "r"(a[3]), "r"(b0), "r"(b1));
}

// scan grid barrier: RED arrive + LOAD-based polling (R8 proven)
__device__ __forceinline__ void gbar(unsigned target) {
    __syncthreads();
    if (threadIdx.x == 0) {
        unsigned* p = &g_cnt;
        asm volatile("red.release.gpu.global.add.u32 [%0], 1;" :: "l"(p) : "memory");
        unsigned v;
        do {
            asm volatile("ld.acquire.gpu.global.u32 %0, [%1];" : "=r"(v) : "l"(p) : "memory");
        } while (v < target);
    }
    __syncthreads();
}

#define CPA16(d, s) asm volatile("cp.async.cg.shared.global [%0], [%1], 16;" :: "r"(d), "l"(s) : "memory")
#define CPC()       asm volatile("cp.async.commit_group;" ::: "memory")
#define CPW(n)      asm volatile("cp.async.wait_group %0;" :: "n"(n) : "memory")

// ---------------- W_fc fp32 -> bf16; also zero SUMEXP + counters ----------
__global__ void k_cvt_wfc(const float* __restrict__ wfc)
{
    const size_t i = (size_t)blockIdx.x * 256 + threadIdx.x;
    float4 v = ((const float4*)wfc)[i];
    __nv_bfloat162 lo = __floats2bfloat162_rn(v.x, v.y);
    __nv_bfloat162 hi = __floats2bfloat162_rn(v.z, v.w);
    uint2 o; o.x = *(uint32_t*)&lo; o.y = *(uint32_t*)&hi;
    ((uint2*)g_WFCb)[i] = o;
    if (i < MROWS) g_SUMEXP[i] = 0.f;
    if (i == 0) { g_cnt = 0; g_tick = 0; }
}

// ---------------- h0 = tanh(ctx @ W_init^T + b_init) via bf16 mma ---------
// grid 4 (n-tiles of 128), 256 threads. M = 128 rows (l*64+b), K = 512.
__global__ void k_h0(const float* __restrict__ ctx,
                     const float* __restrict__ W_init,
                     const float* __restrict__ b_init)
{
    const int bn = blockIdx.x * 128;
    const int tid = threadIdx.x;
    const int wid = tid >> 5, lane = tid & 31;
    const int warp_m = wid >> 2, warp_n = wid & 3;
    const int g = lane >> 2, tg = lane & 3;

    __shared__ __nv_bfloat16 As[128][72];
    __shared__ __nv_bfloat16 Bs[128][72];
    __shared__ float bsm[128];
    if (tid < 128) bsm[tid] = b_init[bn + tid];
    __syncthreads();

    float acc[4][4][4];
#pragma unroll
    for (int i = 0; i < 4; i++)
#pragma unroll
        for (int j = 0; j < 4; j++)
#pragma unroll
            for (int r = 0; r < 4; r++) acc[i][j][r] = 0.f;

    for (int k0 = 0; k0 < HSZ; k0 += 64) {
        for (int i = tid; i < 2048; i += 256) {
            const int r = i >> 4, q = i & 15;
            float4 v = *(const float4*)(ctx + (size_t)r * HSZ + k0 + q * 4);
            __nv_bfloat162 p0 = __floats2bfloat162_rn(v.x, v.y);
            __nv_bfloat162 p1 = __floats2bfloat162_rn(v.z, v.w);
            uint2 u; u.x = *(uint32_t*)&p0; u.y = *(uint32_t*)&p1;
            *(uint2*)&As[r][q * 4] = u;
        }
        for (int i = tid; i < 2048; i += 256) {
            const int r = i >> 4, q = i & 15;
            float4 v = *(const float4*)(W_init + (size_t)(bn + r) * HSZ + k0 + q * 4);
            __nv_bfloat162 p0 = __floats2bfloat162_rn(v.x, v.y);
            __nv_bfloat162 p1 = __floats2bfloat162_rn(v.z, v.w);
            uint2 u; u.x = *(uint32_t*)&p0; u.y = *(uint32_t*)&p1;
            *(uint2*)&Bs[r][q * 4] = u;
        }
        __syncthreads();
#pragma unroll
        for (int kk = 0; kk < 64; kk += 16) {
            uint32_t af[4][4], bfr[4][2];
#pragma unroll
            for (int im = 0; im < 4; im++) {
                int r0 = warp_m * 64 + im * 16;
                af[im][0] = *(const uint32_t*)&As[r0 + g    ][kk + tg*2    ];
                af[im][1] = *(const uint32_t*)&As[r0 + g + 8][kk + tg*2    ];
                af[im][2] = *(const uint32_t*)&As[r0 + g    ][kk + tg*2 + 8];
                af[im][3] = *(const uint32_t*)&As[r0 + g + 8][kk + tg*2 + 8];
            }
#pragma unroll
            for (int in_ = 0; in_ < 4; in_++) {
                int c0 = warp_n * 32 + in_ * 8;
                bfr[in_][0] = *(const uint32_t*)&Bs[c0 + g][kk + tg*2    ];
                bfr[in_][1] = *(const uint32_t*)&Bs[c0 + g][kk + tg*2 + 8];
            }
#pragma unroll
            for (int im = 0; im < 4; im++)
#pragma unroll
                for (int in_ = 0; in_ < 4; in_++)
                    mma16816(acc[im][in_], af[im], bfr[in_][0], bfr[in_][1]);
        }
        __syncthreads();
    }

#pragma unroll
    for (int im = 0; im < 4; im++) {
#pragma unroll
        for (int half = 0; half < 2; half++) {
            const int row = warp_m * 64 + im * 16 + g + half * 8;   // l*64+b
            const int l = row >> 6, b = row & 63;
            float*         hout  = (l == 0) ? g_HA  : g_HB;
            __nv_bfloat16* houtb = (l == 0) ? g_HAb : g_HBb;
#pragma unroll
            for (int in_ = 0; in_ < 4; in_++) {
                const int col_l = warp_n * 32 + in_ * 8 + tg * 2;
#pragma unroll
                for (int cc = 0; cc < 2; cc++) {
                    const int j = bn + col_l + cc;
                    const float v = tanhf(acc[im][in_][half*2 + cc] + bsm[col_l + cc]);
                    hout[b * HSZ + j]  = v;
                    houtb[b * HSZ + j] = __float2bfloat16(v);
                }
            }
        }
    }
}

// ---------------- GI0 = gather(emb) @ Wi0^T + bi0 (bf16 mma) --------------
__global__ void k_gi0(const float* __restrict__ emb,
                      const int*   __restrict__ targets,
                      const float* __restrict__ Wi0,
                      const float* __restrict__ bi0)
{
    const int bn = blockIdx.x * 128;
    const int bm = blockIdx.y * 128;
    const int tid = threadIdx.x;
    const int wid = tid >> 5, lane = tid & 31;
    const int warp_m = wid >> 2, warp_n = wid & 3;
    const int g = lane >> 2, tg = lane & 3;

    __shared__ __nv_bfloat16 As[128][72];
    __shared__ __nv_bfloat16 Bs[128][72];
    __shared__ float bsm[128];
    __shared__ int   toks[128];
    if (tid < 128) {
        bsm[tid] = bi0[bn + tid];
        int row = bm + tid; if (row >= MROWS) row = MROWS - 1;
        const int t = row >> 6, b = row & 63;
        toks[tid] = (t == 0) ? 1 : targets[b * TSZ + t - 1];
    }
    __syncthreads();

    float acc[4][4][4];
#pragma unroll
    for (int i = 0; i < 4; i++)
#pragma unroll
        for (int j = 0; j < 4; j++)
#pragma unroll
            for (int r = 0; r < 4; r++) acc[i][j][r] = 0.f;

    for (int k0 = 0; k0 < ESZ; k0 += 64) {
        for (int i = tid; i < 2048; i += 256) {
            const int r = i >> 4, q = i & 15;
            float4 v = *(const float4*)(emb + (size_t)toks[r] * ESZ + k0 + q * 4);
            __nv_bfloat162 p0 = __floats2bfloat162_rn(v.x, v.y);
            __nv_bfloat162 p1 = __floats2bfloat162_rn(v.z, v.w);
            uint2 u; u.x = *(uint32_t*)&p0; u.y = *(uint32_t*)&p1;
            *(uint2*)&As[r][q * 4] = u;
        }
        for (int i = tid; i < 2048; i += 256) {
            const int r = i >> 4, q = i & 15;
            float4 v = *(const float4*)(Wi0 + (size_t)(bn + r) * ESZ + k0 + q * 4);
            __nv_bfloat162 p0 = __floats2bfloat162_rn(v.x, v.y);
            __nv_bfloat162 p1 = __floats2bfloat162_rn(v.z, v.w);
            uint2 u; u.x = *(uint32_t*)&p0; u.y = *(uint32_t*)&p1;
            *(uint2*)&Bs[r][q * 4] = u;
        }
        __syncthreads();
#pragma unroll
        for (int kk = 0; kk < 64; kk += 16) {
            uint32_t af[4][4], bfr[4][2];
#pragma unroll
            for (int im = 0; im < 4; im++) {
                int r0 = warp_m * 64 + im * 16;
                af[im][0] = *(const uint32_t*)&As[r0 + g    ][kk + tg*2    ];
                af[im][1] = *(const uint32_t*)&As[r0 + g + 8][kk + tg*2    ];
                af[im][2] = *(const uint32_t*)&As[r0 + g    ][kk + tg*2 + 8];
                af[im][3] = *(const uint32_t*)&As[r0 + g + 8][kk + tg*2 + 8];
            }
#pragma unroll
            for (int in_ = 0; in_ < 4; in_++) {
                int c0 = warp_n * 32 + in_ * 8;
                bfr[in_][0] = *(const uint32_t*)&Bs[c0 + g][kk + tg*2    ];
                bfr[in_][1] = *(const uint32_t*)&Bs[c0 + g][kk + tg*2 + 8];
            }
#pragma unroll
            for (int im = 0; im < 4; im++)
#pragma unroll
                for (int in_ = 0; in_ < 4; in_++)
                    mma16816(acc[im][in_], af[im], bfr[in_][0], bfr[in_][1]);
        }
        __syncthreads();
    }

#pragma unroll
    for (int im = 0; im < 4; im++) {
#pragma unroll
        for (int half = 0; half < 2; half++) {
            const int row = bm + warp_m * 64 + im * 16 + g + half * 8;
            if (row >= MROWS) continue;
#pragma unroll
            for (int in_ = 0; in_ < 4; in_++) {
                const int col_l = warp_n * 32 + in_ * 8 + tg * 2;
                float2 st;
                st.x = acc[im][in_][half*2 + 0] + bsm[col_l];
                st.y = acc[im][in_][half*2 + 1] + bsm[col_l + 1];
                *(float2*)(g_GI0 + (size_t)row * G3 + bn + col_l) = st;
            }
        }
    }
}

// ---------------- FUSED: scan (CTAs 0-63) + 192x128 logits consumers ------
__global__ void __launch_bounds__(NT, 1) k_fused(
    const float* __restrict__ Wh0, const float* __restrict__ bh0,
    const float* __restrict__ Wi1, const float* __restrict__ Wh1,
    const float* __restrict__ bi1, const float* __restrict__ bh1,
    const float* __restrict__ b_fc, float* __restrict__ out)
{
    extern __shared__ __nv_bfloat16 smb[];
    __shared__ int s_w;

    const int tid  = threadIdx.x;
    const int wid  = tid >> 5, lane = tid & 31;
    const int g    = lane >> 2, tg = lane & 3;

    // =================== SCAN ROLE (CTAs 0..63) ===================
    if (blockIdx.x < NC) {
        __nv_bfloat16* Wh0s = smb;
        __nv_bfloat16* Wi1s = smb + 24 * WB;
        __nv_bfloat16* Wh1s = smb + 48 * WB;
        __nv_bfloat16* Ax   = smb + 72 * WB;
        __nv_bfloat16* Ah   = Ax  + 64 * WB;
        float4* accS = (float4*)(smb + 200 * WB);

        const int mt   = wid & 3;
        const int mat  = wid >> 2;
        const int m0   = mt * 16;
        const int jb   = blockIdx.x * JC;

        for (int idx = tid; idx < 24 * 128; idx += NT) {
            const int row = idx >> 7, q = idx & 127;
            const int gate = row >> 3, jj = row & 7;
            const size_t grow = (size_t)(gate * HSZ + jb + jj) * HSZ + q * 4;
            const int o = row * WB + q * 4;
            float4 v0 = *(const float4*)(Wh0 + grow);
            float4 v1 = *(const float4*)(Wi1 + grow);
            float4 v2 = *(const float4*)(Wh1 + grow);
            __nv_bfloat162 p0, p1; uint2 u;
            p0 = __floats2bfloat162_rn(v0.x, v0.y); p1 = __floats2bfloat162_rn(v0.z, v0.w);
            u.x = *(uint32_t*)&p0; u.y = *(uint32_t*)&p1; *(uint2*)(Wh0s + o) = u;
            p0 = __floats2bfloat162_rn(v1.x, v1.y); p1 = __floats2bfloat162_rn(v1.z, v1.w);
            u.x = *(uint32_t*)&p0; u.y = *(uint32_t*)&p1; *(uint2*)(Wi1s + o) = u;
            p0 = __floats2bfloat162_rn(v2.x, v2.y); p1 = __floats2bfloat162_rn(v2.z, v2.w);
            u.x = *(uint32_t*)&p0; u.y = *(uint32_t*)&p1; *(uint2*)(Wh1s + o) = u;
        }
        __syncthreads();

        float bg0[3][2], bgi1[3][2], bgh1[3][2];
#pragma unroll
        for (int gi = 0; gi < 3; gi++)
#pragma unroll
            for (int cc = 0; cc < 2; cc++) {
                const int j = gi * HSZ + jb + 2 * tg + cc;
                bg0[gi][cc]  = bh0[j];
                bgi1[gi][cc] = bi1[j];
                bgh1[gi][cc] = bh1[j];
            }

        auto mma3 = [&](const __nv_bfloat16* A, const __nv_bfloat16* W, float acc[3][4]) {
            const __nv_bfloat16* Ar0 = A + (m0 + g) * WB;
            const __nv_bfloat16* Ar1 = Ar0 + 8 * WB;
#pragma unroll
            for (int gi = 0; gi < 3; gi++)
#pragma unroll
                for (int r = 0; r < 4; r++) acc[gi][r] = 0.f;
#pragma unroll
            for (int ks = 0; ks < 32; ks++) {
                const int k = ks * 16;
                uint32_t a[4];
                a[0] = *(const uint32_t*)(Ar0 + k + tg * 2);
                a[1] = *(const uint32_t*)(Ar1 + k + tg * 2);
                a[2] = *(const uint32_t*)(Ar0 + k + 8 + tg * 2);
                a[3] = *(const uint32_t*)(Ar1 + k + 8 + tg * 2);
#pragma unroll
                for (int gi = 0; gi < 3; gi++) {
                    const __nv_bfloat16* br = W + (gi * 8 + g) * WB + k + tg * 2;
                    mma16816(acc[gi], a, *(const uint32_t*)br, *(const uint32_t*)(br + 8));
                }
            }
        };

        auto epi0 = [&](int tt, const float acc0[3][4]) {
            const float* hAin = g_HA + (tt & 1) * BH;
            float* hAout = g_HA + ((tt & 1) ^ 1) * BH;
            __nv_bfloat16* hAbout = g_HAb + ((tt & 1) ^ 1) * BH;
#pragma unroll
            for (int hf = 0; hf < 2; hf++) {
                const int b = m0 + g + 8 * hf;
                const float* gi0p = g_GI0 + ((size_t)tt * BSZ + b) * G3;
#pragma unroll
                for (int cc = 0; cc < 2; cc++) {
                    const int j = jb + 2 * tg + cc;
                    const float r = sigf(__ldg(gi0p + j)          + acc0[0][hf*2+cc] + bg0[0][cc]);
                    const float z = sigf(__ldg(gi0p + HSZ + j)    + acc0[1][hf*2+cc] + bg0[1][cc]);
                    const float n = tanhf(__ldg(gi0p + 2*HSZ + j) + r * (acc0[2][hf*2+cc] + bg0[2][cc]));
                    const float hprev = __ldcg(hAin + (size_t)b * HSZ + j);
                    const float v = (1.f - z) * n + z * hprev;
                    hAout[(size_t)b * HSZ + j]  = v;
                    hAbout[(size_t)b * HSZ + j] = __float2bfloat16(v);
                }
            }
        };

        // prologue: cell0(t=0)
        {
            for (int idx = tid; idx < 64 * 64; idx += NT) {
                const int r = idx >> 6, q = idx & 63;
                *(uint4*)(Ax + r * WB + q * 8) =
                    __ldcg((const uint4*)(g_HAb + (size_t)r * HSZ + q * 8));
            }
            __syncthreads();
            if (mat == 1) {
                float acc0[3][4];
                mma3(Ax, Wh0s, acc0);
                epi0(0, acc0);
            }
        }
        gbar(NC);

        for (int t = 0; t < TSZ; t++) {
            const int cur = t & 1, nxt = cur ^ 1;

            {
                const __nv_bfloat16* srcA = g_HAb + (size_t)nxt * BH;
                const __nv_bfloat16* srcB = g_HBb + (size_t)cur * BH;
                for (int idx = tid; idx < 128 * 64; idx += NT) {
                    const int r = idx >> 6, q = idx & 63;
                    if (r < 64)
                        *(uint4*)(Ax + r * WB + q * 8) =
                            __ldcg((const uint4*)(srcA + (size_t)r * HSZ + q * 8));
                    else
                        *(uint4*)(Ah + (r - 64) * WB + q * 8) =
                            __ldcg((const uint4*)(srcB + (size_t)(r - 64) * HSZ + q * 8));
                }
            }
            __syncthreads();

            float acc[3][4];
            if (mat == 0)      mma3(Ax, Wi1s, acc);
            else if (mat == 1) mma3(Ax, Wh0s, acc);
            else               mma3(Ah, Wh1s, acc);

            if (mat == 0) {
#pragma unroll
                for (int gi = 0; gi < 3; gi++) {
                    float4 v; v.x = acc[gi][0]; v.y = acc[gi][1]; v.z = acc[gi][2]; v.w = acc[gi][3];
                    accS[((wid & 3) * 3 + gi) * 32 + lane] = v;
                }
            }
            __syncthreads();

            if (mat == 2) {
                const float* hBin = g_HB + (size_t)cur * BH;
                float* hBout = g_HB + (size_t)nxt * BH;
                __nv_bfloat16* hBbout = g_HBb + (size_t)nxt * BH;
                float accx[3][4];
#pragma unroll
                for (int gi = 0; gi < 3; gi++) {
                    float4 v = accS[((wid & 3) * 3 + gi) * 32 + lane];
                    accx[gi][0] = v.x; accx[gi][1] = v.y; accx[gi][2] = v.z; accx[gi][3] = v.w;
                }
#pragma unroll
                for (int hf = 0; hf < 2; hf++) {
                    const int b = m0 + g + 8 * hf;
#pragma unroll
                    for (int cc = 0; cc < 2; cc++) {
                        const int j = jb + 2 * tg + cc;
                        const float r = sigf(accx[0][hf*2+cc] + bgi1[0][cc] + acc[0][hf*2+cc] + bgh1[0][cc]);
                        const float z = sigf(accx[1][hf*2+cc] + bgi1[1][cc] + acc[1][hf*2+cc] + bgh1[1][cc]);
                        const float n = tanhf(accx[2][hf*2+cc] + bgi1[2][cc]
                                              + r * (acc[2][hf*2+cc] + bgh1[2][cc]));
                        const float hprev = __ldcg(hBin + (size_t)b * HSZ + j);
                        const float v = (1.f - z) * n + z * hprev;
                        hBout[(size_t)b * HSZ + j]  = v;
                        hBbout[(size_t)b * HSZ + j] = __float2bfloat16(v);
                        g_YSb[((size_t)t * BSZ + b) * HSZ + j] = __float2bfloat16(v);  // [t*64+b]
                    }
                }
            } else if (mat == 1 && t < TSZ - 1) {
                epi0(t + 1, acc);
            }

            if (t < TSZ - 1) gbar((unsigned)(t + 2) * NC);
        }

        // publish final step (t=64) writes
        __syncthreads();
        if (tid == 0)
            asm volatile("red.release.gpu.global.add.u32 [%0], 1;" :: "l"(&g_cnt) : "memory");
    }

    // =================== CONSUMER ROLE: 192m x 128n tiles, 12 warps ========
    {
        __nv_bfloat16* As = smb;                       // [2][192][72]
        __nv_bfloat16* Bs = smb + 2 * AS_BUF;          // [2][128][72]
        float* bsm = (float*)(Bs + 2 * BS_BUF);        // 128
        float* ses = bsm + 128;                        // 192

        const int warp_m = wid >> 2, warp_n = wid & 3; // 3 x 4 warps

        for (;;) {
            if (tid == 0) s_w = (int)atomicAdd(&g_tick, 1u);
            __syncthreads();
            const int w = s_w;
            if (w >= NITEM) break;
            const int mu = w / 250, nb = w % 250;
            const int bm = mu * 192, bn = nb * 128;
            const int need_t = (3 * mu + 2 < TSZ - 1) ? (3 * mu + 2) : (TSZ - 1);
            const unsigned wait_val = (unsigned)(need_t + 2) * NC;

            if (tid == 0) {
                unsigned v;
                for (;;) {
                    asm volatile("ld.acquire.gpu.global.u32 %0, [%1];" : "=r"(v) : "l"(&g_cnt) : "memory");
                    if (v >= wait_val) break;
                    __nanosleep(256);
                }
            }
            if (tid < 128) bsm[tid] = b_fc[bn + tid];
            if (tid < 192) ses[tid] = 0.f;
            __syncthreads();

            float acc[4][4][4];
#pragma unroll
            for (int i = 0; i < 4; i++)
#pragma unroll
                for (int j = 0; j < 4; j++)
#pragma unroll
                    for (int r = 0; r < 4; r++) acc[i][j][r] = 0.f;

            {
#pragma unroll
                for (int it = 0; it < 4; it++) {
                    const int idx = it * NT + tid;
                    const int r = idx >> 3, q = idx & 7;
                    int row = bm + r; if (row >= MROWS) row = MROWS - 1;
                    uint32_t d = (uint32_t)__cvta_generic_to_shared(As + r * LG_STRIDE + q * 8);
                    CPA16(d, g_YSb + (size_t)row * HSZ + q * 8);
                }
                for (int idx = tid; idx < 1024; idx += NT) {
                    const int r = idx >> 3, q = idx & 7;
                    uint32_t d = (uint32_t)__cvta_generic_to_shared(Bs + r * LG_STRIDE + q * 8);
                    CPA16(d, g_WFCb + (size_t)(bn + r) * HSZ + q * 8);
                }
            }
            CPC();

            for (int i = 0; i < 8; i++) {
                const int p = i & 1;
                if (i + 1 < 8) {
                    const int k0 = (i + 1) * 64, pn = p ^ 1;
#pragma unroll
                    for (int it = 0; it < 4; it++) {
                        const int idx = it * NT + tid;
                        const int r = idx >> 3, q = idx & 7;
                        int row = bm + r; if (row >= MROWS) row = MROWS - 1;
                        uint32_t d = (uint32_t)__cvta_generic_to_shared(As + pn * AS_BUF + r * LG_STRIDE + q * 8);
                        CPA16(d, g_YSb + (size_t)row * HSZ + k0 + q * 8);
                    }
                    for (int idx = tid; idx < 1024; idx += NT) {
                        const int r = idx >> 3, q = idx & 7;
                        uint32_t d = (uint32_t)__cvta_generic_to_shared(Bs + pn * BS_BUF + r * LG_STRIDE + q * 8);
                        CPA16(d, g_WFCb + (size_t)(bn + r) * HSZ + k0 + q * 8);
                    }
                    CPC(); CPW(1);
                } else CPW(0);
                __syncthreads();

                const __nv_bfloat16* Ap = As + p * AS_BUF;
                const __nv_bfloat16* Bp = Bs + p * BS_BUF;
#pragma unroll
                for (int kk = 0; kk < 64; kk += 16) {
                    uint32_t af[4][4], bfr[4][2];
#pragma unroll
                    for (int im = 0; im < 4; im++) {
                        int r0 = warp_m * 64 + im * 16;
                        af[im][0] = *(const uint32_t*)(Ap + (r0 + g    ) * LG_STRIDE + kk + tg*2    );
                        af[im][1] = *(const uint32_t*)(Ap + (r0 + g + 8) * LG_STRIDE + kk + tg*2    );
                        af[im][2] = *(const uint32_t*)(Ap + (r0 + g    ) * LG_STRIDE + kk + tg*2 + 8);
                        af[im][3] = *(const uint32_t*)(Ap + (r0 + g + 8) * LG_STRIDE + kk + tg*2 + 8);
                    }
#pragma unroll
                    for (int in_ = 0; in_ < 4; in_++) {
                        int c0 = warp_n * 32 + in_ * 8;
                        bfr[in_][0] = *(const uint32_t*)(Bp + (c0 + g) * LG_STRIDE + kk + tg*2    );
                        bfr[in_][1] = *(const uint32_t*)(Bp + (c0 + g) * LG_STRIDE + kk + tg*2 + 8);
                    }
#pragma unroll
                    for (int im = 0; im < 4; im++)
#pragma unroll
                        for (int in_ = 0; in_ < 4; in_++)
                            mma16816(acc[im][in_], af[im], bfr[in_][0], bfr[in_][1]);
                }
                __syncthreads();
            }

#pragma unroll
            for (int im = 0; im < 4; im++) {
#pragma unroll
                for (int half = 0; half < 2; half++) {
                    const int row_l = warp_m * 64 + im * 16 + g + half * 8;
                    const int r_ys = bm + row_l;
                    if (r_ys >= MROWS) continue;
                    const int orow = (r_ys & 63) * TSZ + (r_ys >> 6);
                    float s = 0.f;
#pragma unroll
                    for (int in_ = 0; in_ < 4; in_++) {
                        const int col_l = warp_n * 32 + in_ * 8 + tg * 2;
                        float v0 = acc[im][in_][half*2 + 0] + bsm[col_l];
                        float v1 = acc[im][in_][half*2 + 1] + bsm[col_l + 1];
                        float2 st; st.x = v0; st.y = v1;
                        *(float2*)(out + (size_t)orow * VSZ + bn + col_l) = st;
                        s += __expf(v0) + __expf(v1);
                    }
                    atomicAdd(&ses[row_l], s);
                }
            }
            __syncthreads();
            if (tid < 192) {
                const int r_ys = bm + tid;
                if (r_ys < MROWS) {
                    const int orow = (r_ys & 63) * TSZ + (r_ys >> 6);
                    atomicAdd(&g_SUMEXP[orow], ses[tid]);
                }
            }
            __syncthreads();
        }
    }
}

// ---------------- fixup: out -= log(sumexp(row)), 4 float4/thread ---------
__global__ void k_fix(float* __restrict__ out)
{
    const size_t base = (size_t)blockIdx.x * 1024 + threadIdx.x;
#pragma unroll
    for (int it = 0; it < 4; it++) {
        const size_t i = base + it * 256;
        const int row = (int)(i / (VSZ / 4));
        const float l = __logf(g_SUMEXP[row]);
        float4 v = ((const float4*)out)[i];
        v.x -= l; v.y -= l; v.z -= l; v.w -= l;
        ((float4*)out)[i] = v;
    }
}

// ---------------- launch ---------------------------------------------------
extern "C" void kernel_launch(void* const* d_in, const int* in_sizes, int n_in,
                              void* d_out, int out_size)
{
    const float* ctx     = (const float*)d_in[0];
    const int*   targets = (const int*)  d_in[1];
    const float* emb     = (const float*)d_in[2];
    const float* W_init  = (const float*)d_in[3];
    const float* b_init  = (const float*)d_in[4];
    const float* Wi0     = (const float*)d_in[5];
    const float* Wh0     = (const float*)d_in[6];
    const float* bi0     = (const float*)d_in[7];
    const float* bh0     = (const float*)d_in[8];
    const float* Wi1     = (const float*)d_in[9];
    const float* Wh1     = (const float*)d_in[10];
    const float* bi1     = (const float*)d_in[11];
    const float* bh1     = (const float*)d_in[12];
    const float* W_fc    = (const float*)d_in[13];
    const float* b_fc    = (const float*)d_in[14];
    float* out = (float*)d_out;

    static int smem_set = 0;
    const int fused_smem = 200 * WB * 2 + 4 * 3 * 32 * 16;   // 214,144 B
    if (!smem_set) {
        cudaFuncSetAttribute(k_fused, cudaFuncAttributeMaxDynamicSharedMemorySize, fused_smem);
        smem_set = 1;
    }

    k_cvt_wfc<<<(VSZ * HSZ / 4) / 256, 256>>>(W_fc);
    k_h0<<<4, 256>>>(ctx, W_init, b_init);
    k_gi0<<<dim3(G3 / 128, (MROWS + 127) / 128), 256>>>(emb, targets, Wi0, bi0);

    k_fused<<<NCTA, NT, fused_smem>>>(Wh0, bh0, Wi1, Wh1, bi1, bh1, b_fc, out);

    k_fix<<<(int)(((size_t)MROWS * VSZ / 4) / 1024), 256>>>(out);
}